// round 17
// baseline (speedup 1.0000x reference)
#include <cuda_runtime.h>
#include <cuda_fp16.h>
#include <cstdint>

// Problem constants
#define N_FEAT  65536
#define N_PROTO 512
#define DIMK    256

#define UNIT_M   64                 // feature rows per work unit
#define N_UNITS  (N_FEAT / UNIT_M)  // 1024
#define BLK_N    16                 // protos per chunk (2 ntiles)
#define N_CHUNKS 8                  // chunks per quarter (8 * 16 = 128 protos)

// SMEM layout (bytes)
#define SM_PSQ   0                          // 512 floats = 2048 B
#define SM_B     4096                       // 2 bufs * 4 quarters * 8192 B = 65536
#define BUF_BYTES 32768                     // one buffer = 4 quarter-slabs
#define SMEM_TOTAL (SM_B + 2 * BUF_BYTES)   // 69632 B

// pack float2 -> fp16x2 (x -> low half)
__device__ __forceinline__ uint32_t pk(float2 f) {
    __half2 h = __floats2half2_rn(f.x, f.y);
    return *(uint32_t*)&h;
}

// m16n8k16 fp16 MMA, fp32 accumulate
__device__ __forceinline__ void mma_f16(float d[4], const uint4& a,
                                        uint32_t b0, uint32_t b1) {
    asm volatile(
        "mma.sync.aligned.m16n8k16.row.col.f32.f16.f16.f32 "
        "{%0,%1,%2,%3}, {%4,%5,%6,%7}, {%8,%9}, {%0,%1,%2,%3};"
        : "+f"(d[0]), "+f"(d[1]), "+f"(d[2]), "+f"(d[3])
        : "r"(a.x), "r"(a.y), "r"(a.z), "r"(a.w),
          "r"(b0), "r"(b1));
}

// ---------------------------------------------------------------------------
// Persistent-CTA version of R16: grid = #SMs; each CTA grid-strides over 1024
// units of (64 rows x 512 protos), eliminating wave quantization (2nd wave
// was only 71% full at grid=256). Inner machinery identical to R16:
// A fragments in registers (16 uint4/warp), mainloop k-step = 1 LDS.128 ->
// 2 MMAs, chunk c-1's 12 stores interleaved into chunk c's k-steps.
// Warp grid 4(M) x 4(N): warp owns 16 rows + a 128-proto quarter.
//   B PAIR slab (quarter q, kstep s): 32 lanes x uint4 = 512 B,
//     uint4 = {b0(u=0), b1(u=0), b0(u=1), b1(u=1)}
// ---------------------------------------------------------------------------
__global__ void __launch_bounds__(512, 1) proto_dist_kernel(
    const float* __restrict__ feat,
    const float* __restrict__ proto,
    float* __restrict__ out1,    // [N, P]
    float* __restrict__ out2)    // [P, N]
{
    extern __shared__ char smem[];
    float* s_psq = (float*)(smem + SM_PSQ);

    const int tid  = threadIdx.x;
    const int lane = tid & 31;
    const int wid  = tid >> 5;     // 0..15
    const int g    = lane >> 2;
    const int tig  = lane & 3;

    const int mi   = wid >> 2;     // 0..3 — M position within unit (16 rows)
    const int nj   = wid & 3;      // 0..3 — proto quarter

    // ---- All 512 prototype norms, exact fp32, ONCE per CTA ----
    {
        const float4* r = (const float4*)(proto + (size_t)tid * DIMK);
        float s0 = 0.f, s1 = 0.f, s2 = 0.f, s3 = 0.f;
#pragma unroll
        for (int j = 0; j < 64; j += 4) {
            float4 v0 = r[j], v1 = r[j + 1], v2 = r[j + 2], v3 = r[j + 3];
            s0 += v0.x * v0.x + v0.y * v0.y + v0.z * v0.z + v0.w * v0.w;
            s1 += v1.x * v1.x + v1.y * v1.y + v1.z * v1.z + v1.w * v1.w;
            s2 += v2.x * v2.x + v2.y * v2.y + v2.z * v2.z + v2.w * v2.w;
            s3 += v3.x * v3.x + v3.y * v3.y + v3.z * v3.z + v3.w * v3.w;
        }
        s_psq[tid] = (s0 + s1) + (s2 + s3);
    }

    const int pgrp = nj * 128;   // this warp's proto quarter base

    // ---- B staging: warp (mi, nj) stages ksteps [4mi, 4mi+4) of quarter
    //      nj's pair-slab for chunk c into buffer buf ----
    auto stage_B = [&](int c, char* buf) {
        const int p0 = pgrp + c * BLK_N;
        const float* r0 = proto + (size_t)(p0 + g) * DIMK;       // ntile u=0
        const float* r1 = proto + (size_t)(p0 + 8 + g) * DIMK;   // ntile u=1
        char* dst = buf + nj * 8192 + (size_t)lane * 16;
#pragma unroll
        for (int j = 0; j < 4; j++) {
            const int s  = mi * 4 + j;
            const int kA = s * 16 + 2 * tig;
            float2 f0 = *(const float2*)(r0 + kA);
            float2 f2 = *(const float2*)(r0 + kA + 8);
            float2 f1 = *(const float2*)(r1 + kA);
            float2 f3 = *(const float2*)(r1 + kA + 8);
            uint4 w;
            w.x = pk(f0); w.y = pk(f2);   // b0,b1 of u=0
            w.z = pk(f1); w.w = pk(f3);   // b0,b1 of u=1
            *(uint4*)(dst + (size_t)s * 512) = w;
        }
    };

    const int plq = 2 * tig;
    char* const buf0 = smem + SM_B;
    char* const buf1 = smem + SM_B + BUF_BYTES;

    for (int u = blockIdx.x; u < N_UNITS; u += gridDim.x) {
        const int m0 = u * UNIT_M;

        // ---- A rows into REGISTERS (16 uint4) + exact fp32 feature norms ----
        uint4 aF[16];
        float fs0, fs1;
        {
            const float* rA = feat + (size_t)(m0 + mi * 16 + g) * DIMK;
            const float* rB = rA + 8 * DIMK;
            float sqA = 0.f, sqB = 0.f;
#pragma unroll
            for (int s = 0; s < 16; s++) {
                const int kA = s * 16 + 2 * tig;
                float2 f0 = *(const float2*)(rA + kA);
                float2 f1 = *(const float2*)(rB + kA);
                float2 f2 = *(const float2*)(rA + kA + 8);
                float2 f3 = *(const float2*)(rB + kA + 8);
                sqA += f0.x * f0.x + f0.y * f0.y + f2.x * f2.x + f2.y * f2.y;
                sqB += f1.x * f1.x + f1.y * f1.y + f3.x * f3.x + f3.y * f3.y;
                aF[s].x = pk(f0); aF[s].y = pk(f1); aF[s].z = pk(f2); aF[s].w = pk(f3);
            }
            sqA += __shfl_xor_sync(0xffffffffu, sqA, 1);
            sqA += __shfl_xor_sync(0xffffffffu, sqA, 2);
            sqB += __shfl_xor_sync(0xffffffffu, sqB, 1);
            sqB += __shfl_xor_sync(0xffffffffu, sqB, 2);
            fs0 = sqA;   // norm of row m0 + 16*mi + g
            fs1 = sqB;   // norm of row m0 + 16*mi + g + 8
        }

        // Per-unit epilogue constants
        const int ml0 = mi * 16 + g, ml1 = ml0 + 8;
        float* const row1a = out1 + (size_t)(m0 + ml0) * N_PROTO;
        float* const row1b = out1 + (size_t)(m0 + ml1) * N_PROTO;
        float* const col2a = out2 + (m0 + ml0);   // + p*N_FEAT
        float* const col2b = out2 + (m0 + ml1);

        float accA[2][4], accB[2][4];

        // compute accC from bufC; store pend (chunk at offset p0p) if has_pend
        auto run_chunk = [&](float (&accC)[2][4], float (&pend)[2][4],
                             const char* bufC, bool has_pend, int p0p) {
#pragma unroll
            for (int up = 0; up < 2; up++)
#pragma unroll
                for (int e = 0; e < 4; e++) accC[up][e] = 0.f;

            if (has_pend) {
#pragma unroll
                for (int up = 0; up < 2; up++) {
                    const float2 ps = *(const float2*)(s_psq + p0p + plq + up * 8);
                    float* d = pend[up];
                    d[0] = fs0 + ps.x - 2.0f * d[0];
                    d[1] = fs0 + ps.y - 2.0f * d[1];
                    d[2] = fs1 + ps.x - 2.0f * d[2];
                    d[3] = fs1 + ps.y - 2.0f * d[3];
                }
            }

            const char* bB = bufC + nj * 8192 + (size_t)lane * 16;

#pragma unroll
            for (int s = 0; s < 16; s++) {
                const uint4 bp = *(const uint4*)(bB + (size_t)s * 512);
                mma_f16(accC[0], aF[s], bp.x, bp.y);
                mma_f16(accC[1], aF[s], bp.z, bp.w);

                if (has_pend && s < 12) {
                    if (s < 4) {
                        // out1 [N,P]: 4 tig-lanes x float2 = full 32B sector
                        const int up = s & 1;
                        const float* d = pend[up];
                        if (s < 2) *(float2*)(row1a + p0p + plq + up * 8) = make_float2(d[0], d[1]);
                        else       *(float2*)(row1b + p0p + plq + up * 8) = make_float2(d[2], d[3]);
                    } else {
                        // out2 [P,N]: 8 g-lanes x 4B = full 32B sector per column
                        const int q  = s - 4;          // 0..7
                        const int up = q >> 2;         // 0,1
                        const int cc = (q >> 1) & 1;   // column: pl or pl+1
                        const int rr = q & 1;          // row half: a or b
                        const size_t off = (size_t)(p0p + plq + up * 8 + cc) * N_FEAT;
                        const float* d = pend[up];
                        if (rr == 0) col2a[off] = d[cc];
                        else         col2b[off] = d[2 + cc];
                    }
                }
            }
        };

        stage_B(0, buf0);
        __syncthreads();   // psq (unit 0) + B(chunk 0) visible; prev unit's bufs free

        for (int c2 = 0; c2 < N_CHUNKS / 2; c2++) {
            const int cA = 2 * c2, cB = 2 * c2 + 1;
            // phase A: compute chunk cA (buf0); store chunk cA-1 (accB)
            stage_B(cB, buf1);
            run_chunk(accA, accB, buf0, c2 > 0, pgrp + (cA - 1) * BLK_N);
            __syncthreads();   // buf1 ready; buf0 consumed
            // phase B: compute chunk cB (buf1); store chunk cA (accA)
            if (cB + 1 < N_CHUNKS) stage_B(cB + 1, buf0);
            run_chunk(accB, accA, buf1, true, pgrp + cA * BLK_N);
            __syncthreads();   // buf0 ready; buf1 consumed
        }

        // ---- unit tail: store chunk N_CHUNKS-1 from accB ----
        {
            const int p0p = pgrp + (N_CHUNKS - 1) * BLK_N;
#pragma unroll
            for (int up = 0; up < 2; up++) {
                const int pl = plq + up * 8;
                const float2 ps = *(const float2*)(s_psq + p0p + pl);
                float* d = accB[up];
                d[0] = fs0 + ps.x - 2.0f * d[0];
                d[1] = fs0 + ps.y - 2.0f * d[1];
                d[2] = fs1 + ps.x - 2.0f * d[2];
                d[3] = fs1 + ps.y - 2.0f * d[3];
                *(float2*)(row1a + p0p + pl) = make_float2(d[0], d[1]);
                *(float2*)(row1b + p0p + pl) = make_float2(d[2], d[3]);
                col2a[(size_t)(p0p + pl)     * N_FEAT] = d[0];
                col2a[(size_t)(p0p + pl + 1) * N_FEAT] = d[1];
                col2b[(size_t)(p0p + pl)     * N_FEAT] = d[2];
                col2b[(size_t)(p0p + pl + 1) * N_FEAT] = d[3];
            }
        }
    }
}

// ---------------------------------------------------------------------------
// Launch: grid = #SMs (persistent), computed at launch time.
// ---------------------------------------------------------------------------
extern "C" void kernel_launch(void* const* d_in, const int* in_sizes, int n_in,
                              void* d_out, int out_size)
{
    (void)in_sizes; (void)n_in; (void)out_size;
    const float* feat  = (const float*)d_in[0];
    const float* proto = (const float*)d_in[1];
    float* out1 = (float*)d_out;
    float* out2 = out1 + (size_t)N_FEAT * N_PROTO;

    static int nsm = 0;
    if (nsm == 0) {
        cudaDeviceGetAttribute(&nsm, cudaDevAttrMultiProcessorCount, 0);
        if (nsm <= 0) nsm = 148;
    }

    cudaFuncSetAttribute(proto_dist_kernel,
                         cudaFuncAttributeMaxDynamicSharedMemorySize, SMEM_TOTAL);

    proto_dist_kernel<<<nsm, 512, SMEM_TOTAL>>>(feat, proto, out1, out2);
}